// round 1
// baseline (speedup 1.0000x reference)
#include <cuda_runtime.h>

#define NN 4096
#define TT 300
#define TW 10          // 320 bits >= 300 timesteps
#define NB 32          // persistent blocks (must all be co-resident)
#define NTHR 512       // 4 i-groups x 128 columns

// ---------------- device scratch (no allocations allowed) ----------------
__device__ unsigned g_mask[NN * TW];        // bit t of inp[t][i], i-major
__device__ float    g_X[TT * NN];           // precomputed inp @ W
__device__ int      g_list[NN * TT];        // monotonic spike index list
__device__ unsigned g_total_count;          // monotonic append counter (reset per launch)
__device__ unsigned g_bar_count;            // barrier arrivals (returns to 0)
__device__ unsigned g_bar_epoch;            // barrier release epoch (monotonic)
__device__ unsigned g_pub_end;              // spike-list length published at barrier

// ---------------- kernel 1: pack inp bits, i-major ----------------
__global__ void pack_kernel(const int* __restrict__ inp) {
    int i = blockIdx.x * blockDim.x + threadIdx.x;
    if (i >= NN) return;
    for (int w = 0; w < TW; ++w) {
        unsigned word = 0u;
        int tbase = w * 32;
        #pragma unroll
        for (int b = 0; b < 32; ++b) {
            int t = tbase + b;
            if (t < TT)
                word |= (((unsigned)inp[(size_t)t * NN + i]) & 1u) << b;
        }
        g_mask[i * TW + w] = word;
    }
}

// ---------------- kernel 2: X[t][j] = sum_{i: inp[t][i]=1} W[i][j] ----------------
// grid (16 col-chunks of 256 cols, 10 t-words), 128 threads, 2 cols/thread,
// packed f32x2 predicated adds.
__global__ void __launch_bounds__(128) input_gemm_kernel(const float* __restrict__ w) {
    const int tid = threadIdx.x;
    const int j0 = blockIdx.x * 256 + 2 * tid;
    const int word = blockIdx.y;

    unsigned long long acc[32];
    #pragma unroll
    for (int b = 0; b < 32; ++b) acc[b] = 0ULL;

    for (int i = 0; i < NN; ++i) {
        float2 wv = *(const float2*)(w + (size_t)i * NN + j0);
        unsigned bits = g_mask[i * TW + word];   // broadcast load across warp
        unsigned long long wpair =
            ((unsigned long long)__float_as_uint(wv.y) << 32) |
            (unsigned long long)__float_as_uint(wv.x);
        #pragma unroll
        for (int b = 0; b < 32; ++b) {
            asm("{\n\t"
                ".reg .pred p;\n\t"
                "setp.ne.b32 p, %1, 0;\n\t"
                "@p add.rn.f32x2 %0, %0, %2;\n\t"
                "}"
                : "+l"(acc[b])
                : "r"(bits & (1u << b)), "l"(wpair));
        }
    }

    #pragma unroll
    for (int b = 0; b < 32; ++b) {
        int t = word * 32 + b;
        if (t < TT) {
            float2 o;
            o.x = __uint_as_float((unsigned)(acc[b] & 0xffffffffULL));
            o.y = __uint_as_float((unsigned)(acc[b] >> 32));
            *(float2*)(g_X + (size_t)t * NN + j0) = o;
        }
    }
}

// ---------------- grid barrier (epoch-based, replay-safe) ----------------
__device__ __forceinline__ void grid_barrier(unsigned e0, unsigned cnt, unsigned* sh_end) {
    __syncthreads();
    if (threadIdx.x == 0) {
        __threadfence();
        unsigned old = atomicAdd(&g_bar_count, 1u);
        if (old == NB - 1u) {
            __threadfence();   // acquire: see all arrivers' prior stores
            g_pub_end = *(volatile unsigned*)&g_total_count;
            *(volatile unsigned*)&g_bar_count = 0u;
            __threadfence();   // release: publish before epoch bump
            atomicAdd(&g_bar_epoch, 1u);
        } else {
            while (((*(volatile unsigned*)&g_bar_epoch) - e0) < cnt) { }
        }
        __threadfence();       // acquire before reading published data
        *sh_end = *(volatile unsigned*)&g_pub_end;
    }
    __syncthreads();
}

// ---------------- kernel 3: persistent recurrent LIF ----------------
__global__ void __launch_bounds__(NTHR) lif_kernel(const float* __restrict__ w_rec,
                                                   float* __restrict__ out) {
    __shared__ float part[3][128];
    __shared__ unsigned sh_end;

    const int tid = threadIdx.x;
    const int g = tid >> 7;          // i-group 0..3
    const int l = tid & 127;         // column within block
    const int j = blockIdx.x * 128 + l;

    unsigned e0 = 0;
    if (tid == 0) e0 = *(volatile unsigned*)&g_bar_epoch;   // epoch base for this launch
    if (blockIdx.x == 0 && tid == 0)
        *(volatile unsigned*)&g_total_count = 0u;           // reset per launch

    unsigned nbar = 1;
    grid_barrier(e0, nbar, &sh_end);        // publishes end = 0
    unsigned prev_end = 0;
    unsigned seg_end = sh_end;              // = 0

    float v = 0.f, rt = 0.f, tl = 1.f;
    const float DECAY = 0.99004983374916805f;   // exp(-1/100) rounded to fp32

    for (int t = 0; t < TT; ++t) {
        // gather recurrent input over spikes of previous step
        float x = 0.f;
        unsigned k = prev_end + (unsigned)g;
        unsigned end = seg_end;
        while (k + 12u < end) {
            int i0 = __ldcg(g_list + k);
            int i1 = __ldcg(g_list + k + 4);
            int i2 = __ldcg(g_list + k + 8);
            int i3 = __ldcg(g_list + k + 12);
            float a0 = w_rec[(size_t)i0 * NN + j];
            float a1 = w_rec[(size_t)i1 * NN + j];
            float a2 = w_rec[(size_t)i2 * NN + j];
            float a3 = w_rec[(size_t)i3 * NN + j];
            x += a0; x += a1; x += a2; x += a3;
            k += 16u;
        }
        while (k < end) {
            x += w_rec[(size_t)__ldcg(g_list + k) * NN + j];
            k += 4u;
        }
        if (g > 0) part[g - 1][l] = x;
        __syncthreads();

        if (g == 0) {
            float xt = x + part[0][l] + part[1][l] + part[2][l]
                     + g_X[(size_t)t * NN + j];
            // LIF dynamics (exact reference order)
            v *= DECAY;
            float xin = (rt > 0.f) ? 0.f : xt;
            rt -= 1.f;
            v += xin;
            bool sp = (v >= 10.f);
            if (sp) { tl = (float)t / 300.0f; rt = 1.f; v = 0.f; }
            out[(size_t)t * NN + j]                        = sp ? 1.f : 0.f;
            out[(size_t)TT * NN + (size_t)t * NN + j]      = tl;
            out[2 * (size_t)TT * NN + (size_t)t * NN + j]  = v;

            // warp-aggregated spike append
            unsigned ball = __ballot_sync(0xffffffffu, sp);
            if (ball) {
                unsigned base = 0;
                if ((tid & 31) == 0)
                    base = atomicAdd(&g_total_count, (unsigned)__popc(ball));
                base = __shfl_sync(0xffffffffu, base, 0);
                if (sp)
                    g_list[base + __popc(ball & ((1u << (tid & 31)) - 1u))] = j;
            }
            __threadfence();   // publish list entries before barrier arrival
        }

        ++nbar;
        grid_barrier(e0, nbar, &sh_end);
        prev_end = end;
        seg_end = sh_end;
    }
}

// ---------------- launch ----------------
extern "C" void kernel_launch(void* const* d_in, const int* in_sizes, int n_in,
                              void* d_out, int out_size) {
    const int* inp; const float* w; const float* w_rec;
    // expected order: inp [T*N] int32, w [N*N] f32, w_rec [N*N] f32
    if (in_sizes[0] == TT * NN) {
        inp = (const int*)d_in[0]; w = (const float*)d_in[1]; w_rec = (const float*)d_in[2];
    } else if (n_in > 1 && in_sizes[1] == TT * NN) {
        inp = (const int*)d_in[1]; w = (const float*)d_in[0]; w_rec = (const float*)d_in[2];
    } else {
        inp = (const int*)d_in[2]; w = (const float*)d_in[0]; w_rec = (const float*)d_in[1];
    }
    float* out = (float*)d_out;

    pack_kernel<<<16, 256>>>(inp);
    input_gemm_kernel<<<dim3(16, 10), 128>>>(w);
    lif_kernel<<<NB, NTHR>>>(w_rec, out);
}

// round 2
// speedup vs baseline: 1.0291x; 1.0291x over previous
#include <cuda_runtime.h>

#define NN   4096
#define TT   300
#define TW   10          // 320 bits >= 300 timesteps
#define NBLK 128         // persistent blocks (must all be co-resident; 148 SMs)
#define NTHR 256

// ---------------- device scratch (static globals; no allocations) ----------------
__device__ unsigned           g_mask[NN * TW];          // bit t of inp[t][i], i-major
__device__ float              g_Xpart[4ull * 320 * NN]; // 4 i-quarter partials of inp@W
__device__ unsigned long long g_slot[2][NBLK];          // {tag,mask} per block, dbl-buffered
__device__ unsigned           g_bar_count;
__device__ unsigned           g_bar_epoch;

__device__ __forceinline__ unsigned ldvolu(const unsigned* p) {
    unsigned v; asm volatile("ld.volatile.global.b32 %0, [%1];" : "=r"(v) : "l"(p)); return v;
}
__device__ __forceinline__ unsigned long long ldvol64(const unsigned long long* p) {
    unsigned long long v; asm volatile("ld.volatile.global.b64 %0, [%1];" : "=l"(v) : "l"(p)); return v;
}
__device__ __forceinline__ void stvol64(unsigned long long* p, unsigned long long v) {
    asm volatile("st.volatile.global.b64 [%0], %1;" :: "l"(p), "l"(v));
}

// central epoch barrier — used only twice (phase transitions); replay-safe
__device__ __forceinline__ void gbar(unsigned e0, unsigned n) {
    __syncthreads();
    if (threadIdx.x == 0) {
        __threadfence();
        if (atomicAdd(&g_bar_count, 1u) == NBLK - 1u) {
            *(volatile unsigned*)&g_bar_count = 0u;
            __threadfence();
            atomicAdd(&g_bar_epoch, 1u);
        } else {
            while (ldvolu(&g_bar_epoch) - e0 < n) {}
        }
        __threadfence();
    }
    __syncthreads();
}

__global__ void __launch_bounds__(NTHR, 1)
snn_kernel(const int* __restrict__ inp, const float* __restrict__ w,
           const float* __restrict__ w_rec, float* __restrict__ out)
{
    __shared__ unsigned long long Adup[128][18];   // row = 144B (16B aligned)
    __shared__ float part[8][33];

    const int tid = threadIdx.x;
    const int bid = blockIdx.x;

    unsigned e0 = 0;
    if (tid == 0) e0 = ldvolu(&g_bar_epoch);       // read before any arrival -> uniform

    // ---------------- phase 0: pack inp bits + clear spike slots ----------------
    if (tid == 0) { g_slot[0][bid] = 0ull; g_slot[1][bid] = 0ull; }
    for (int u = bid * NTHR + tid; u < NN * TW; u += NBLK * NTHR) {
        int word = u % TW;
        int i    = u / TW;
        unsigned m = 0u;
        int tb = word * 32;
        #pragma unroll
        for (int b = 0; b < 32; ++b) {
            int t = tb + b;
            if (t < TT) m |= (((unsigned)inp[(size_t)t * NN + i]) & 1u) << b;
        }
        g_mask[i * TW + word] = m;
    }
    gbar(e0, 1);

    // ---------------- phase 1: X partials via packed f32x2 FFMA (exact) ----------
    // tile = (cc 0..15 colchunk of 256, q 0..3 i-quarter, word 0..9); 640 tiles = 5/block
    for (int tile = bid; tile < 640; tile += NBLK) {
        int word = tile % 10;
        int ccq  = tile / 10;
        int cc   = ccq >> 2;
        int q    = ccq & 3;
        int j    = cc * 256 + tid;
        int ibase = q * 1024;

        unsigned long long acc[16];
        #pragma unroll
        for (int k = 0; k < 16; ++k) acc[k] = 0ull;

        for (int sub = 0; sub < 8; ++sub) {
            int ib = ibase + sub * 128;
            __syncthreads();
            // convert 128 i x 16 t-pairs of bits -> packed {f32,f32} 0/1 values
            for (int e = tid; e < 2048; e += NTHR) {
                int ii = e >> 4, tp = e & 15;
                unsigned m  = g_mask[(ib + ii) * TW + word];
                unsigned lo = (m >> (2 * tp))     & 1u ? 0x3f800000u : 0u;
                unsigned hi = (m >> (2 * tp + 1)) & 1u ? 0x3f800000u : 0u;
                Adup[ii][tp] = ((unsigned long long)hi << 32) | lo;
            }
            __syncthreads();
            for (int ii = 0; ii < 128; ++ii) {
                unsigned wu = __float_as_uint(w[(size_t)(ib + ii) * NN + j]);
                unsigned long long wp;
                asm("mov.b64 %0, {%1, %1};" : "=l"(wp) : "r"(wu));
                const ulonglong2* ap = (const ulonglong2*)(&Adup[ii][0]);
                #pragma unroll
                for (int k = 0; k < 8; ++k) {
                    ulonglong2 a2 = ap[k];
                    asm("fma.rn.f32x2 %0, %1, %2, %0;" : "+l"(acc[2*k])   : "l"(wp), "l"(a2.x));
                    asm("fma.rn.f32x2 %0, %1, %2, %0;" : "+l"(acc[2*k+1]) : "l"(wp), "l"(a2.y));
                }
            }
        }
        #pragma unroll
        for (int tp = 0; tp < 16; ++tp) {
            int t0 = word * 32 + 2 * tp;
            g_Xpart[((size_t)q * 320 + t0)     * NN + j] = __uint_as_float((unsigned)acc[tp]);
            g_Xpart[((size_t)q * 320 + t0 + 1) * NN + j] = __uint_as_float((unsigned)(acc[tp] >> 32));
        }
    }
    gbar(e0, 2);

    // ---------------- phase 2: barrier-free recurrent LIF ------------------------
    const int l = tid & 31;        // column within block's 32-col slice
    const int g = tid >> 5;        // spike-word group 0..7 (16 words each)
    const int j = bid * 32 + l;

    float v = 0.f, rt = 0.f, tl = 1.f;
    const float DECAY = 0.99004983374916805f;   // fp32(exp(-1/100))

    for (int t = 0; t < TT; ++t) {
        // prefetch input-drive partials early (hide DRAM latency behind gather)
        float x0 = 0.f, x1 = 0.f, x2 = 0.f, x3 = 0.f;
        if (g == 0) {
            x0 = g_Xpart[(size_t)(0 * 320 + t) * NN + j];
            x1 = g_Xpart[(size_t)(1 * 320 + t) * NN + j];
            x2 = g_Xpart[(size_t)(2 * 320 + t) * NN + j];
            x3 = g_Xpart[(size_t)(3 * 320 + t) * NN + j];
        }
        float x = 0.f;
        if (t > 0) {
            const unsigned long long* slot = g_slot[(t - 1) & 1];
            unsigned want = (unsigned)t;                 // tag = step+1, step = t-1
            for (int wd = g * 16; wd < g * 16 + 16; ++wd) {
                unsigned long long u;
                do { u = ldvol64(&slot[wd]); } while ((unsigned)(u >> 32) != want);
                unsigned bits = (unsigned)u;
                while (bits) {
                    int b = __ffs(bits) - 1;
                    bits &= bits - 1u;
                    x += __ldcg(&w_rec[(size_t)(wd * 32 + b) * NN + j]);
                }
            }
        }
        part[g][l] = x;
        __syncthreads();
        if (g == 0) {
            float xt = ((part[0][l] + part[1][l]) + (part[2][l] + part[3][l]))
                     + ((part[4][l] + part[5][l]) + (part[6][l] + part[7][l]))
                     + ((x0 + x1) + (x2 + x3));
            // LIF dynamics, exact reference order
            v *= DECAY;
            float xin = (rt > 0.f) ? 0.f : xt;
            rt -= 1.f;
            v += xin;
            bool sp = (v >= 10.f);
            if (sp) { tl = (float)t / 300.0f; rt = 1.f; v = 0.f; }
            out[(size_t)t * NN + j]            = sp ? 1.f : 0.f;
            out[(size_t)(TT + t) * NN + j]     = tl;
            out[(size_t)(2 * TT + t) * NN + j] = v;

            unsigned ball = __ballot_sync(0xffffffffu, sp);
            if (l == 0)
                stvol64(&g_slot[t & 1][bid],
                        ((unsigned long long)(t + 1) << 32) | (unsigned long long)ball);
        }
        __syncthreads();   // protects part[] (write-after-read) for next step
    }
}

// ---------------- launch ----------------
extern "C" void kernel_launch(void* const* d_in, const int* in_sizes, int n_in,
                              void* d_out, int out_size) {
    const int* inp; const float* w; const float* w_rec;
    if (in_sizes[0] == TT * NN) {
        inp = (const int*)d_in[0]; w = (const float*)d_in[1]; w_rec = (const float*)d_in[2];
    } else if (n_in > 1 && in_sizes[1] == TT * NN) {
        inp = (const int*)d_in[1]; w = (const float*)d_in[0]; w_rec = (const float*)d_in[2];
    } else {
        inp = (const int*)d_in[2]; w = (const float*)d_in[0]; w_rec = (const float*)d_in[1];
    }
    snn_kernel<<<NBLK, NTHR>>>(inp, w, w_rec, (float*)d_out);
}

// round 3
// speedup vs baseline: 1.2017x; 1.1678x over previous
#include <cuda_runtime.h>

#define NN   4096
#define TT   300
#define TW   10          // 320 bits >= 300 timesteps
#define NBLK 128         // persistent blocks (co-resident on 148 SMs)
#define NTHR 256

// ---------------- device scratch (static globals; no allocations) ----------------
__device__ unsigned g_mask[NN * TW];          // bit t of inp[t][i], i-major
__device__ float    g_Xpart[4ull * 320 * NN]; // 4 i-quarter partials of inp@W
__device__ unsigned g_spkw[TT][NBLK];         // spike word per block per step
__device__ int      g_cnt[TT];                // producer count per step (cleared per launch)
__device__ unsigned g_bar_count;
__device__ unsigned g_bar_epoch;

__device__ __forceinline__ unsigned ldvolu(const unsigned* p) {
    unsigned v; asm volatile("ld.volatile.global.b32 %0, [%1];" : "=r"(v) : "l"(p)); return v;
}
__device__ __forceinline__ int ldvoli(const int* p) {
    int v; asm volatile("ld.volatile.global.s32 %0, [%1];" : "=r"(v) : "l"(p)); return v;
}
__device__ __forceinline__ void stcg32(unsigned* p, unsigned v) {
    asm volatile("st.global.cg.b32 [%0], %1;" :: "l"(p), "r"(v));
}

// central epoch barrier — used only for phase transitions; replay-safe
__device__ __forceinline__ void gbar(unsigned e0, unsigned n) {
    __syncthreads();
    if (threadIdx.x == 0) {
        __threadfence();
        if (atomicAdd(&g_bar_count, 1u) == NBLK - 1u) {
            *(volatile unsigned*)&g_bar_count = 0u;
            __threadfence();
            atomicAdd(&g_bar_epoch, 1u);
        } else {
            while (ldvolu(&g_bar_epoch) - e0 < n) {}
        }
        __threadfence();
    }
    __syncthreads();
}

__global__ void __launch_bounds__(NTHR, 1)
snn_kernel(const int* __restrict__ inp, const float* __restrict__ w,
           const float* __restrict__ w_rec, float* __restrict__ out)
{
    __shared__ unsigned long long Adup[128][18];   // phase-1 activation tiles
    __shared__ float part[8][33];                  // phase-2 partial sums

    const int tid = threadIdx.x;
    const int bid = blockIdx.x;

    unsigned e0 = 0;
    if (tid == 0) e0 = ldvolu(&g_bar_epoch);       // epoch base (read before any arrival)

    // ---------------- phase 0: pack inp bits + clear per-step counters ----------
    for (int u = bid * NTHR + tid; u < TT; u += NBLK * NTHR) g_cnt[u] = 0;
    for (int u = bid * NTHR + tid; u < NN * TW; u += NBLK * NTHR) {
        int word = u % TW;
        int i    = u / TW;
        unsigned m = 0u;
        int tb = word * 32;
        #pragma unroll
        for (int b = 0; b < 32; ++b) {
            int t = tb + b;
            if (t < TT) m |= (((unsigned)inp[(size_t)t * NN + i]) & 1u) << b;
        }
        g_mask[i * TW + word] = m;
    }
    gbar(e0, 1);

    // ---------------- phase 1: X partials via packed f32x2 FFMA (exact) ----------
    for (int tile = bid; tile < 640; tile += NBLK) {
        int word = tile % 10;
        int ccq  = tile / 10;
        int cc   = ccq >> 2;
        int q    = ccq & 3;
        int j    = cc * 256 + tid;
        int ibase = q * 1024;

        unsigned long long acc[16];
        #pragma unroll
        for (int k = 0; k < 16; ++k) acc[k] = 0ull;

        for (int sub = 0; sub < 8; ++sub) {
            int ib = ibase + sub * 128;
            __syncthreads();
            for (int e = tid; e < 2048; e += NTHR) {
                int ii = e >> 4, tp = e & 15;
                unsigned m  = g_mask[(ib + ii) * TW + word];
                unsigned lo = (m >> (2 * tp))     & 1u ? 0x3f800000u : 0u;
                unsigned hi = (m >> (2 * tp + 1)) & 1u ? 0x3f800000u : 0u;
                Adup[ii][tp] = ((unsigned long long)hi << 32) | lo;
            }
            __syncthreads();
            for (int ii = 0; ii < 128; ++ii) {
                unsigned wu = __float_as_uint(w[(size_t)(ib + ii) * NN + j]);
                unsigned long long wp;
                asm("mov.b64 %0, {%1, %1};" : "=l"(wp) : "r"(wu));
                const ulonglong2* ap = (const ulonglong2*)(&Adup[ii][0]);
                #pragma unroll
                for (int k = 0; k < 8; ++k) {
                    ulonglong2 a2 = ap[k];
                    asm("fma.rn.f32x2 %0, %1, %2, %0;" : "+l"(acc[2*k])   : "l"(wp), "l"(a2.x));
                    asm("fma.rn.f32x2 %0, %1, %2, %0;" : "+l"(acc[2*k+1]) : "l"(wp), "l"(a2.y));
                }
            }
        }
        #pragma unroll
        for (int tp = 0; tp < 16; ++tp) {
            int t0 = word * 32 + 2 * tp;
            g_Xpart[((size_t)q * 320 + t0)     * NN + j] = __uint_as_float((unsigned)acc[tp]);
            g_Xpart[((size_t)q * 320 + t0 + 1) * NN + j] = __uint_as_float((unsigned)(acc[tp] >> 32));
        }
    }
    gbar(e0, 2);

    // ---------------- phase 2: recurrent LIF, O(1)-latency handshake ------------
    const int l = tid & 31;        // lane
    const int wp = tid >> 5;       // warp 0..7
    const int j = bid * 32 + l;    // this block's 32 output columns

    // gather word ranges for warps 1..7: 18,18,18,18,18,18,20 (=128 words)
    const int wstart = (wp >= 1) ? 18 * (wp - 1) : 0;
    const int wcnt   = (wp == 7) ? 20 : 18;

    float v = 0.f, rt = 0.f, tl = 1.f;
    const float DECAY = 0.99004983374916805f;   // fp32(exp(-1/100))

    for (int t = 0; t < TT; ++t) {
        float x0 = 0.f, x1 = 0.f, x2 = 0.f, x3 = 0.f;
        float x = 0.f;

        if (wp == 0) {
            // warp 0: prefetch input drive only (no gather, no poll)
            x0 = g_Xpart[(size_t)(0 * 320 + t) * NN + j];
            x1 = g_Xpart[(size_t)(1 * 320 + t) * NN + j];
            x2 = g_Xpart[(size_t)(2 * 320 + t) * NN + j];
            x3 = g_Xpart[(size_t)(3 * 320 + t) * NN + j];
        } else if (t > 0) {
            // single-address poll (lane 0 only, light backoff)
            if (l == 0) {
                int c = ldvoli(&g_cnt[t - 1]);
                while (c < NBLK) { __nanosleep(40); c = ldvoli(&g_cnt[t - 1]); }
            }
            __syncwarp();
            __threadfence();   // acquire: spike words now visible in L2
            // one parallel wave reads this warp's words; share via shfl
            unsigned myw = 0u;
            if (l < wcnt) myw = __ldcg(&g_spkw[t - 1][wstart + l]);
            for (int k = 0; k < wcnt; ++k) {
                unsigned bits = __shfl_sync(0xffffffffu, myw, k);
                int base = (wstart + k) << 5;
                while (bits) {
                    int b = __ffs(bits) - 1;
                    bits &= bits - 1u;
                    x += __ldcg(&w_rec[(size_t)(base + b) * NN + j]);
                }
            }
        }
        part[wp][l] = x;
        __syncthreads();

        if (wp == 0) {
            float xt = ((part[1][l] + part[2][l]) + (part[3][l] + part[4][l]))
                     + ((part[5][l] + part[6][l]) + part[7][l])
                     + ((x0 + x1) + (x2 + x3));
            // LIF dynamics, exact reference order
            v *= DECAY;
            float xin = (rt > 0.f) ? 0.f : xt;
            rt -= 1.f;
            v += xin;
            bool sp = (v >= 10.f);
            if (sp) { tl = (float)t / 300.0f; rt = 1.f; v = 0.f; }

            // publish FIRST (shortens inter-block chain), then write outputs
            unsigned ball = __ballot_sync(0xffffffffu, sp);
            if (t < TT - 1 && l == 0) {
                stcg32(&g_spkw[t][bid], ball);
                __threadfence();
                atomicAdd(&g_cnt[t], 1);
            }
            out[(size_t)t * NN + j]            = sp ? 1.f : 0.f;
            out[(size_t)(TT + t) * NN + j]     = tl;
            out[(size_t)(2 * TT + t) * NN + j] = v;
        }
        __syncthreads();   // part[] WAR protection for next step
    }
}

// ---------------- launch ----------------
extern "C" void kernel_launch(void* const* d_in, const int* in_sizes, int n_in,
                              void* d_out, int out_size) {
    const int* inp; const float* w; const float* w_rec;
    if (in_sizes[0] == TT * NN) {
        inp = (const int*)d_in[0]; w = (const float*)d_in[1]; w_rec = (const float*)d_in[2];
    } else if (n_in > 1 && in_sizes[1] == TT * NN) {
        inp = (const int*)d_in[1]; w = (const float*)d_in[0]; w_rec = (const float*)d_in[2];
    } else {
        inp = (const int*)d_in[2]; w = (const float*)d_in[0]; w_rec = (const float*)d_in[1];
    }
    snn_kernel<<<NBLK, NTHR>>>(inp, w, w_rec, (float*)d_out);
}